// round 7
// baseline (speedup 1.0000x reference)
#include <cuda_runtime.h>
#include <math.h>

#define Bsz 128
#define Nn  512
#define Ff  64
#define Dd  64
#define Kk  20
#define BN  (Bsz*Nn)          // 65536
#define NELEM (BN*Dd)         // 4194304
#define ATTN_BLOCKS Bsz       // 128 (one block per batch)
#define H1_BLOCKS   1024

// ---------------- device scratch (no allocations allowed) ----------------
__device__ float d_g[NELEM];
__device__ float d_agg[NELEM];
__device__ float d_enorm[Nn*Dd];
__device__ float d_si[BN];
__device__ float d_sj[BN];
__device__ float d_eai[Nn];
__device__ float d_eaj[Nn];
__device__ int   d_topk[Nn*Kk];
__device__ float d_ps1[64*ATTN_BLOCKS];   // channel-major BN1 partials
__device__ float d_pq1[64*ATTN_BLOCKS];
__device__ float d_ps2[64*H1_BLOCKS];     // channel-major BN2 partials
__device__ float d_pq2[64*H1_BLOCKS];
__device__ float d_scale1[64], d_shift1[64], d_scale2[64], d_shift2[64];

__device__ __forceinline__ float warpSum(float v){
  #pragma unroll
  for(int o=16;o;o>>=1) v += __shfl_xor_sync(0xffffffffu, v, o);
  return v;
}
__device__ __forceinline__ float warpMax(float v){
  #pragma unroll
  for(int o=16;o;o>>=1) v = fmaxf(v, __shfl_xor_sync(0xffffffffu, v, o));
  return v;
}
__device__ __forceinline__ float f4c(const float4& v, int j){
  return j==0 ? v.x : (j==1 ? v.y : (j==2 ? v.z : v.w));
}

// ---- K1: normalize embed rows, per-node embed-attention scalars ----
__global__ void k_embed(const float* __restrict__ embed,
                        const float* __restrict__ aemi,
                        const float* __restrict__ aemj){
  int gw   = (blockIdx.x*blockDim.x + threadIdx.x) >> 5;
  int lane = threadIdx.x & 31;
  if(gw >= Nn) return;
  float v0 = embed[gw*64+lane];
  float v1 = embed[gw*64+32+lane];
  float ss = warpSum(v0*v0 + v1*v1);
  float inv = 1.0f/(sqrtf(ss)+1e-12f);
  d_enorm[gw*64+lane]    = v0*inv;
  d_enorm[gw*64+32+lane] = v1*inv;
  float si = warpSum(v0*aemi[lane] + v1*aemi[lane+32]);
  float sj = warpSum(v0*aemj[lane] + v1*aemj[lane+32]);
  if(lane==0){ d_eai[gw]=si; d_eaj[gw]=sj; }
}

// ---- K2: warp-per-node topk, sims register-resident ----
__global__ void k_topk(){
  __shared__ float tile[64*68];
  __shared__ float srows[8*68];
  int t = threadIdx.x, w = t>>5, lane = t&31;
  int node = blockIdx.x*8 + w;

  if(t < 128){
    int r = t >> 4, c4 = t & 15;
    float4 v = reinterpret_cast<const float4*>(d_enorm)[(blockIdx.x*8 + r)*16 + c4];
    *reinterpret_cast<float4*>(&srows[r*68 + c4*4]) = v;
  }

  float sims[16];
  #pragma unroll
  for(int chunk=0; chunk<8; chunk++){
    __syncthreads();
    #pragma unroll
    for(int q=0; q<4; q++){
      int idx = t + q*256;
      int r = idx >> 4, c4 = idx & 15;
      float4 v = reinterpret_cast<const float4*>(d_enorm)[(chunk*64 + r)*16 + c4];
      *reinterpret_cast<float4*>(&tile[r*68 + c4*4]) = v;
    }
    __syncthreads();
    const float* sr = &srows[w*68];
    float a0 = 0.f, a1 = 0.f;
    #pragma unroll
    for(int kk=0; kk<64; kk+=4){
      float4 s4 = *reinterpret_cast<const float4*>(&sr[kk]);
      float4 e0 = *reinterpret_cast<const float4*>(&tile[lane*68+kk]);
      float4 e1 = *reinterpret_cast<const float4*>(&tile[(lane+32)*68+kk]);
      a0 += s4.x*e0.x + s4.y*e0.y + s4.z*e0.z + s4.w*e0.w;
      a1 += s4.x*e1.x + s4.y*e1.y + s4.z*e1.z + s4.w*e1.w;
    }
    sims[chunk*2]   = a0;
    sims[chunk*2+1] = a1;
  }

  for(int sel=0; sel<Kk; sel++){
    float bv = -INFINITY; int bj = 0x3fffffff;
    #pragma unroll
    for(int s=0; s<16; s++){
      float v = sims[s];
      int j = (s>>1)*64 + (s&1)*32 + lane;
      if(v > bv || (v == bv && j < bj)){ bv = v; bj = j; }
    }
    #pragma unroll
    for(int o=16; o; o>>=1){
      float ov = __shfl_xor_sync(0xffffffffu, bv, o);
      int   oj = __shfl_xor_sync(0xffffffffu, bj, o);
      if(ov > bv || (ov == bv && oj < bj)){ bv = ov; bj = oj; }
    }
    if(lane==0) d_topk[node*Kk+sel] = bj;
    int wslot = ((bj>>6)<<1) | ((bj>>5)&1);
    bool own = ((bj & 31) == lane);
    #pragma unroll
    for(int s=0; s<16; s++) if(own && s==wslot) sims[s] = -INFINITY;
  }
}

// ---- K3: g = x @ W_lin via 64x64x64 register-tiled block, + s_i/s_j ----
__global__ void k_gemm(const float* __restrict__ x, const float* __restrict__ W,
                       const float* __restrict__ ati, const float* __restrict__ atj){
  __shared__ float Ws[64*68];   // Ws[k*68 + col]
  __shared__ float xs[64*68];   // xs[row*68 + k]
  __shared__ float sdi[64*17], sdj[64*17];
  int t = threadIdx.x;
  int tx = t & 15, ty = t >> 4;

  const float4* W4 = reinterpret_cast<const float4*>(W);
  const float4* X4 = reinterpret_cast<const float4*>(x + blockIdx.x*64*64);
  #pragma unroll
  for(int q=0; q<4; q++){
    int idx = q*256 + t;
    int r = idx >> 4, c4 = idx & 15;
    float4 wv = W4[idx];
    *reinterpret_cast<float4*>(&Ws[r*68 + c4*4]) = wv;
    float4 xv = X4[idx];
    *reinterpret_cast<float4*>(&xs[r*68 + c4*4]) = xv;
  }
  __syncthreads();

  float4 acc0 = make_float4(0.f,0.f,0.f,0.f);
  float4 acc1 = make_float4(0.f,0.f,0.f,0.f);
  float4 acc2 = make_float4(0.f,0.f,0.f,0.f);
  float4 acc3 = make_float4(0.f,0.f,0.f,0.f);
  const float* x0 = &xs[(ty*4+0)*68];
  const float* x1 = &xs[(ty*4+1)*68];
  const float* x2 = &xs[(ty*4+2)*68];
  const float* x3 = &xs[(ty*4+3)*68];
  #pragma unroll
  for(int k4=0; k4<16; k4++){
    float4 xa = *reinterpret_cast<const float4*>(&x0[k4*4]);
    float4 xb = *reinterpret_cast<const float4*>(&x1[k4*4]);
    float4 xc = *reinterpret_cast<const float4*>(&x2[k4*4]);
    float4 xd = *reinterpret_cast<const float4*>(&x3[k4*4]);
    #pragma unroll
    for(int j=0; j<4; j++){
      float4 b4 = *reinterpret_cast<const float4*>(&Ws[(k4*4+j)*68 + tx*4]);
      float a0 = f4c(xa,j), a1 = f4c(xb,j), a2 = f4c(xc,j), a3 = f4c(xd,j);
      acc0.x += a0*b4.x; acc0.y += a0*b4.y; acc0.z += a0*b4.z; acc0.w += a0*b4.w;
      acc1.x += a1*b4.x; acc1.y += a1*b4.y; acc1.z += a1*b4.z; acc1.w += a1*b4.w;
      acc2.x += a2*b4.x; acc2.y += a2*b4.y; acc2.z += a2*b4.z; acc2.w += a2*b4.w;
      acc3.x += a3*b4.x; acc3.y += a3*b4.y; acc3.z += a3*b4.z; acc3.w += a3*b4.w;
    }
  }

  int row0 = blockIdx.x*64 + ty*4;
  *reinterpret_cast<float4*>(&d_g[(row0+0)*64 + tx*4]) = acc0;
  *reinterpret_cast<float4*>(&d_g[(row0+1)*64 + tx*4]) = acc1;
  *reinterpret_cast<float4*>(&d_g[(row0+2)*64 + tx*4]) = acc2;
  *reinterpret_cast<float4*>(&d_g[(row0+3)*64 + tx*4]) = acc3;

  float4 av = *reinterpret_cast<const float4*>(&ati[tx*4]);
  float4 aw = *reinterpret_cast<const float4*>(&atj[tx*4]);
  sdi[(ty*4+0)*17+tx] = acc0.x*av.x+acc0.y*av.y+acc0.z*av.z+acc0.w*av.w;
  sdi[(ty*4+1)*17+tx] = acc1.x*av.x+acc1.y*av.y+acc1.z*av.z+acc1.w*av.w;
  sdi[(ty*4+2)*17+tx] = acc2.x*av.x+acc2.y*av.y+acc2.z*av.z+acc2.w*av.w;
  sdi[(ty*4+3)*17+tx] = acc3.x*av.x+acc3.y*av.y+acc3.z*av.z+acc3.w*av.w;
  sdj[(ty*4+0)*17+tx] = acc0.x*aw.x+acc0.y*aw.y+acc0.z*aw.z+acc0.w*aw.w;
  sdj[(ty*4+1)*17+tx] = acc1.x*aw.x+acc1.y*aw.y+acc1.z*aw.z+acc1.w*aw.w;
  sdj[(ty*4+2)*17+tx] = acc2.x*aw.x+acc2.y*aw.y+acc2.z*aw.z+acc2.w*aw.w;
  sdj[(ty*4+3)*17+tx] = acc3.x*aw.x+acc3.y*aw.y+acc3.z*aw.z+acc3.w*aw.w;
  __syncthreads();
  if(t < 64){
    float si = 0.f, sj = 0.f;
    #pragma unroll
    for(int m=0; m<16; m++){ si += sdi[t*17+m]; sj += sdj[t*17+m]; }
    int grow = blockIdx.x*64 + t;
    int node = grow & (Nn-1);
    d_si[grow] = si + d_eai[node];
    d_sj[grow] = sj + d_eaj[node];
  }
}

// ---- K4: one block per batch, two-phase (softmax table -> shuffle-free gather) ----
// smem: g[32768] + attn[512*21] + si[512] + sj[512] floats + src[512*21] ushort
#define ATTN_F_G    0
#define ATTN_F_ATTN 32768
#define ATTN_F_SI   (32768 + 512*21)        // 43520
#define ATTN_F_SJ   (ATTN_F_SI + 512)
#define ATTN_F_END  (ATTN_F_SJ + 512)       // floats used
#define ATTN_SMEM_BYTES (ATTN_F_END*4 + 512*21*2 + 64)

__global__ void __launch_bounds__(1024,1) k_attn(const float* __restrict__ gnn_bias){
  extern __shared__ float sm[];
  float* g_sm    = sm + ATTN_F_G;
  float* attn_sm = sm + ATTN_F_ATTN;
  float* si_sm   = sm + ATTN_F_SI;
  float* sj_sm   = sm + ATTN_F_SJ;
  unsigned short* src_sm = (unsigned short*)(sm + ATTN_F_END);
  __shared__ float rS[32*64], rQ[32*64];

  int t = threadIdx.x;               // 1024 threads
  int b = blockIdx.x;
  int lane = t & 31, w = t >> 5;

  const float4* gg = reinterpret_cast<const float4*>(d_g) + b*8192;
  float4* g4 = reinterpret_cast<float4*>(g_sm);
  #pragma unroll
  for(int q=0; q<8; q++) g4[q*1024+t] = gg[q*1024+t];
  if(t < 512){ sj_sm[t] = d_sj[b*512+t]; si_sm[t] = d_si[b*512+t]; }
  __syncthreads();

  // ---- phase 1: softmax weights -> smem tables ----
  for(int it=0; it<16; it++){
    int i = w*16 + it;
    int src = (lane < Kk) ? d_topk[i*Kk+lane] : i;   // lane==20 -> self loop
    float z;
    if(lane <= Kk){
      z = si_sm[i] + sj_sm[src];
      z = (z > 0.f) ? z : 0.2f*z;
      if(lane < Kk && src == i) z = -INFINITY;
    } else z = -INFINITY;
    float m = warpMax(z);
    float e = (lane <= Kk) ? __expf(z - m) : 0.f;
    float s = warpSum(e);
    if(lane <= Kk){
      attn_sm[i*21 + lane] = e / s;
      src_sm [i*21 + lane] = (unsigned short)(src*32);  // float2 units
    }
  }
  __syncthreads();

  // ---- phase 2: shuffle-free gather; lane owns channels 2l, 2l+1 ----
  const float2* g2 = reinterpret_cast<const float2*>(g_sm);
  float2 bi2 = reinterpret_cast<const float2*>(gnn_bias)[lane];
  float2 ps = make_float2(0.f,0.f);
  float2 pq = make_float2(0.f,0.f);

  for(int it=0; it<16; it++){
    int i = w*16 + it;
    const float* ar = &attn_sm[i*21];
    const unsigned short* sr = &src_sm[i*21];
    float2 acc = make_float2(0.f,0.f);
    #pragma unroll
    for(int e=0; e<21; e++){
      float a = ar[e];                       // broadcast LDS
      int  s2 = sr[e];                       // broadcast LDS (src*32)
      float2 v = g2[s2 + lane];              // conflict-free LDS.64
      acc.x += a*v.x; acc.y += a*v.y;
    }
    acc.x += bi2.x; acc.y += bi2.y;
    reinterpret_cast<float2*>(&d_agg[(b*512+i)*64])[lane] = acc;
    ps.x += acc.x; ps.y += acc.y;
    pq.x += acc.x*acc.x; pq.y += acc.y*acc.y;
  }
  rS[w*64 + lane*2]   = ps.x;
  rS[w*64 + lane*2+1] = ps.y;
  rQ[w*64 + lane*2]   = pq.x;
  rQ[w*64 + lane*2+1] = pq.y;
  __syncthreads();
  if(t < 64){
    float S=0.f, Q=0.f;
    #pragma unroll
    for(int ww=0; ww<32; ww++){ S += rS[ww*64+t]; Q += rQ[ww*64+t]; }
    d_ps1[t*ATTN_BLOCKS + b] = S;
    d_pq1[t*ATTN_BLOCKS + b] = Q;
  }
}

// ---- K5: reduce BN partials -> scale/shift. block per channel. ----
__global__ void k_red(const float* __restrict__ ps, const float* __restrict__ pq,
                      int nblk, const float* __restrict__ gamma,
                      const float* __restrict__ beta,
                      float* __restrict__ scale, float* __restrict__ shift){
  __shared__ float shS[8], shQ[8];
  int c = blockIdx.x, t = threadIdx.x;
  float s = 0.f, q = 0.f;
  for(int idx=t; idx<nblk; idx+=256){
    s += ps[c*nblk+idx];
    q += pq[c*nblk+idx];
  }
  s = warpSum(s); q = warpSum(q);
  if((t&31)==0){ shS[t>>5]=s; shQ[t>>5]=q; }
  __syncthreads();
  if(t==0){
    float S=0.f, Q=0.f;
    #pragma unroll
    for(int ww=0; ww<8; ww++){ S+=shS[ww]; Q+=shQ[ww]; }
    float mu  = S * (1.0f/(float)BN);
    float var = Q * (1.0f/(float)BN) - mu*mu;
    float sc  = gamma[c] * rsqrtf(var + 1e-5f);
    scale[c] = sc;
    shift[c] = beta[c] - mu*sc;
  }
}

// ---- K6: BN2 stats only (h1 recomputed from agg, never stored) ----
__global__ void k_h1(const float* __restrict__ embed){
  __shared__ float shp[1024], shq2[1024];
  int t = threadIdx.x;
  int d0 = (t & 15) * 4;
  float4 sc1 = *reinterpret_cast<const float4*>(&d_scale1[d0]);
  float4 sh1 = *reinterpret_cast<const float4*>(&d_shift1[d0]);
  float4 psum = make_float4(0.f,0.f,0.f,0.f);
  float4 psq  = make_float4(0.f,0.f,0.f,0.f);
  #pragma unroll
  for(int q=0; q<4; q++){
    int i = blockIdx.x*1024 + q*256 + t;     // (i&15)==(t&15)
    int row  = i >> 4;
    int node = row & (Nn-1);
    float4 a  = reinterpret_cast<const float4*>(d_agg)[i];
    float4 em = reinterpret_cast<const float4*>(embed)[node*16 + (i&15)];
    float4 r;
    r.x = fmaxf(a.x*sc1.x+sh1.x, 0.f)*em.x;
    r.y = fmaxf(a.y*sc1.y+sh1.y, 0.f)*em.y;
    r.z = fmaxf(a.z*sc1.z+sh1.z, 0.f)*em.z;
    r.w = fmaxf(a.w*sc1.w+sh1.w, 0.f)*em.w;
    psum.x += r.x; psum.y += r.y; psum.z += r.z; psum.w += r.w;
    psq.x += r.x*r.x; psq.y += r.y*r.y; psq.z += r.z*r.z; psq.w += r.w*r.w;
  }
  shp[t*4+0]=psum.x; shp[t*4+1]=psum.y; shp[t*4+2]=psum.z; shp[t*4+3]=psum.w;
  shq2[t*4+0]=psq.x; shq2[t*4+1]=psq.y; shq2[t*4+2]=psq.z; shq2[t*4+3]=psq.w;
  __syncthreads();
  if(t < 64){
    int gi = t >> 2, comp = t & 3;
    float S=0.f, Q=0.f;
    #pragma unroll
    for(int m=0; m<16; m++){
      S += shp [(gi + m*16)*4 + comp];
      Q += shq2[(gi + m*16)*4 + comp];
    }
    d_ps2[t*H1_BLOCKS + blockIdx.x] = S;
    d_pq2[t*H1_BLOCKS + blockIdx.x] = Q;
  }
}

// ---- K7: out = relu(bn2(relu(bn1(agg))*embed)) @ out_W + out_b ----
__global__ void k_out(const float* __restrict__ embed,
                      const float* __restrict__ outW, const float* __restrict__ outB,
                      float* __restrict__ out){
  int lane = threadIdx.x & 31, w = threadIdx.x >> 5;
  int sub = lane & 15, half = lane >> 4;
  int row = blockIdx.x*16 + w*2 + half;
  int node = row & (Nn-1);
  float4 a   = *reinterpret_cast<const float4*>(&d_agg[row*64 + sub*4]);
  float4 em  = *reinterpret_cast<const float4*>(&embed[node*64 + sub*4]);
  float4 s1  = *reinterpret_cast<const float4*>(&d_scale1[sub*4]);
  float4 h1_ = *reinterpret_cast<const float4*>(&d_shift1[sub*4]);
  float4 s2  = *reinterpret_cast<const float4*>(&d_scale2[sub*4]);
  float4 h2_ = *reinterpret_cast<const float4*>(&d_shift2[sub*4]);
  float4 ow  = *reinterpret_cast<const float4*>(&outW[sub*4]);
  float hx = fmaxf(a.x*s1.x+h1_.x,0.f)*em.x;
  float hy = fmaxf(a.y*s1.y+h1_.y,0.f)*em.y;
  float hz = fmaxf(a.z*s1.z+h1_.z,0.f)*em.z;
  float hw = fmaxf(a.w*s1.w+h1_.w,0.f)*em.w;
  float p = fmaxf(hx*s2.x+h2_.x,0.f)*ow.x + fmaxf(hy*s2.y+h2_.y,0.f)*ow.y
          + fmaxf(hz*s2.z+h2_.z,0.f)*ow.z + fmaxf(hw*s2.w+h2_.w,0.f)*ow.w;
  #pragma unroll
  for(int o=8; o; o>>=1) p += __shfl_xor_sync(0xffffffffu, p, o);
  if(sub==0) out[row] = p + outB[0];
}

extern "C" void kernel_launch(void* const* d_in, const int* in_sizes, int n_in,
                              void* d_out, int out_size){
  int iData, iEmbed, iW, iAtI, iAtJ, iAemI, iAemJ, iBias, iG1, iB1, iG2, iB2, iOW, iOB;
  if(n_in >= 15 && in_sizes[1] == 2048){
    iData=0; iEmbed=2; iW=3; iAtI=4; iAtJ=5; iAemI=6; iAemJ=7; iBias=8;
    iG1=9; iB1=10; iG2=11; iB2=12; iOW=13; iOB=14;
  } else {
    iData=0; iEmbed=1; iW=2; iAtI=3; iAtJ=4; iAemI=5; iAemJ=6; iBias=7;
    iG1=8; iB1=9; iG2=10; iB2=11; iOW=12; iOB=13;
  }
  const float* data  = (const float*)d_in[iData];
  const float* embed = (const float*)d_in[iEmbed];
  const float* W     = (const float*)d_in[iW];
  const float* atI   = (const float*)d_in[iAtI];
  const float* atJ   = (const float*)d_in[iAtJ];
  const float* aemI  = (const float*)d_in[iAemI];
  const float* aemJ  = (const float*)d_in[iAemJ];
  const float* bias  = (const float*)d_in[iBias];
  const float* g1    = (const float*)d_in[iG1];
  const float* b1    = (const float*)d_in[iB1];
  const float* g2    = (const float*)d_in[iG2];
  const float* b2    = (const float*)d_in[iB2];
  const float* outW  = (const float*)d_in[iOW];
  const float* outB  = (const float*)d_in[iOB];
  float* out = (float*)d_out;

  float *sc1, *sh1, *sc2, *sh2, *ps1, *pq1, *ps2, *pq2;
  cudaGetSymbolAddress((void**)&sc1, d_scale1);
  cudaGetSymbolAddress((void**)&sh1, d_shift1);
  cudaGetSymbolAddress((void**)&sc2, d_scale2);
  cudaGetSymbolAddress((void**)&sh2, d_shift2);
  cudaGetSymbolAddress((void**)&ps1, d_ps1);
  cudaGetSymbolAddress((void**)&pq1, d_pq1);
  cudaGetSymbolAddress((void**)&ps2, d_ps2);
  cudaGetSymbolAddress((void**)&pq2, d_pq2);

  cudaFuncSetAttribute(k_attn, cudaFuncAttributeMaxDynamicSharedMemorySize, ATTN_SMEM_BYTES);

  k_embed<<<64, 256>>>(embed, aemI, aemJ);
  k_topk <<<64, 256>>>();
  k_gemm <<<BN/64, 256>>>(data, W, atI, atJ);
  k_attn <<<ATTN_BLOCKS, 1024, ATTN_SMEM_BYTES>>>(bias);
  k_red  <<<64, 256>>>(ps1, pq1, ATTN_BLOCKS, g1, b1, sc1, sh1);
  k_h1   <<<H1_BLOCKS, 256>>>(embed);
  k_red  <<<64, 256>>>(ps2, pq2, H1_BLOCKS, g2, b2, sc2, sh2);
  k_out  <<<BN/16, 256>>>(embed, outW, outB, out);
}

// round 8
// speedup vs baseline: 1.0316x; 1.0316x over previous
#include <cuda_runtime.h>
#include <math.h>

#define Bsz 128
#define Nn  512
#define Ff  64
#define Dd  64
#define Kk  20
#define BN  (Bsz*Nn)          // 65536
#define NELEM (BN*Dd)         // 4194304
#define ATTN_BLOCKS Bsz       // 128 (one block per batch)
#define H1_BLOCKS   1024

// ---------------- device scratch (no allocations allowed) ----------------
__device__ float d_g[NELEM];
__device__ float d_agg[NELEM];
__device__ float d_enorm[Nn*Dd];
__device__ float d_si[BN];
__device__ float d_sj[BN];
__device__ float d_eai[Nn];
__device__ float d_eaj[Nn];
__device__ int   d_topk[Nn*Kk];
__device__ float d_ps1[64*ATTN_BLOCKS];   // channel-major BN1 partials
__device__ float d_pq1[64*ATTN_BLOCKS];
__device__ float d_ps2[64*H1_BLOCKS];     // channel-major BN2 partials
__device__ float d_pq2[64*H1_BLOCKS];
__device__ float d_scale1[64], d_shift1[64], d_scale2[64], d_shift2[64];

__device__ __forceinline__ float warpSum(float v){
  #pragma unroll
  for(int o=16;o;o>>=1) v += __shfl_xor_sync(0xffffffffu, v, o);
  return v;
}
__device__ __forceinline__ float warpMax(float v){
  #pragma unroll
  for(int o=16;o;o>>=1) v = fmaxf(v, __shfl_xor_sync(0xffffffffu, v, o));
  return v;
}
__device__ __forceinline__ float f4c(const float4& v, int j){
  return j==0 ? v.x : (j==1 ? v.y : (j==2 ? v.z : v.w));
}

// ---- K1: normalize embed rows, per-node embed-attention scalars ----
__global__ void k_embed(const float* __restrict__ embed,
                        const float* __restrict__ aemi,
                        const float* __restrict__ aemj){
  int gw   = (blockIdx.x*blockDim.x + threadIdx.x) >> 5;
  int lane = threadIdx.x & 31;
  if(gw >= Nn) return;
  float v0 = embed[gw*64+lane];
  float v1 = embed[gw*64+32+lane];
  float ss = warpSum(v0*v0 + v1*v1);
  float inv = 1.0f/(sqrtf(ss)+1e-12f);
  d_enorm[gw*64+lane]    = v0*inv;
  d_enorm[gw*64+32+lane] = v1*inv;
  float si = warpSum(v0*aemi[lane] + v1*aemi[lane+32]);
  float sj = warpSum(v0*aemj[lane] + v1*aemj[lane+32]);
  if(lane==0){ d_eai[gw]=si; d_eaj[gw]=sj; }
}

// ---- K2: warp-per-node topk, sims register-resident ----
__global__ void k_topk(){
  __shared__ float tile[64*68];
  __shared__ float srows[8*68];
  int t = threadIdx.x, w = t>>5, lane = t&31;
  int node = blockIdx.x*8 + w;

  if(t < 128){
    int r = t >> 4, c4 = t & 15;
    float4 v = reinterpret_cast<const float4*>(d_enorm)[(blockIdx.x*8 + r)*16 + c4];
    *reinterpret_cast<float4*>(&srows[r*68 + c4*4]) = v;
  }

  float sims[16];
  #pragma unroll
  for(int chunk=0; chunk<8; chunk++){
    __syncthreads();
    #pragma unroll
    for(int q=0; q<4; q++){
      int idx = t + q*256;
      int r = idx >> 4, c4 = idx & 15;
      float4 v = reinterpret_cast<const float4*>(d_enorm)[(chunk*64 + r)*16 + c4];
      *reinterpret_cast<float4*>(&tile[r*68 + c4*4]) = v;
    }
    __syncthreads();
    const float* sr = &srows[w*68];
    float a0 = 0.f, a1 = 0.f;
    #pragma unroll
    for(int kk=0; kk<64; kk+=4){
      float4 s4 = *reinterpret_cast<const float4*>(&sr[kk]);
      float4 e0 = *reinterpret_cast<const float4*>(&tile[lane*68+kk]);
      float4 e1 = *reinterpret_cast<const float4*>(&tile[(lane+32)*68+kk]);
      a0 += s4.x*e0.x + s4.y*e0.y + s4.z*e0.z + s4.w*e0.w;
      a1 += s4.x*e1.x + s4.y*e1.y + s4.z*e1.z + s4.w*e1.w;
    }
    sims[chunk*2]   = a0;
    sims[chunk*2+1] = a1;
  }

  for(int sel=0; sel<Kk; sel++){
    float bv = -INFINITY; int bj = 0x3fffffff;
    #pragma unroll
    for(int s=0; s<16; s++){
      float v = sims[s];
      int j = (s>>1)*64 + (s&1)*32 + lane;
      if(v > bv || (v == bv && j < bj)){ bv = v; bj = j; }
    }
    #pragma unroll
    for(int o=16; o; o>>=1){
      float ov = __shfl_xor_sync(0xffffffffu, bv, o);
      int   oj = __shfl_xor_sync(0xffffffffu, bj, o);
      if(ov > bv || (ov == bv && oj < bj)){ bv = ov; bj = oj; }
    }
    if(lane==0) d_topk[node*Kk+sel] = bj;
    int wslot = ((bj>>6)<<1) | ((bj>>5)&1);
    bool own = ((bj & 31) == lane);
    #pragma unroll
    for(int s=0; s<16; s++) if(own && s==wslot) sims[s] = -INFINITY;
  }
}

// ---- K3: g = x @ W_lin via 64x64x64 register-tiled block, + s_i/s_j ----
__global__ void k_gemm(const float* __restrict__ x, const float* __restrict__ W,
                       const float* __restrict__ ati, const float* __restrict__ atj){
  __shared__ float Ws[64*68];   // Ws[k*68 + col]
  __shared__ float xs[64*68];   // xs[row*68 + k]
  __shared__ float sdi[64*17], sdj[64*17];
  int t = threadIdx.x;
  int tx = t & 15, ty = t >> 4;

  const float4* W4 = reinterpret_cast<const float4*>(W);
  const float4* X4 = reinterpret_cast<const float4*>(x + blockIdx.x*64*64);
  #pragma unroll
  for(int q=0; q<4; q++){
    int idx = q*256 + t;
    int r = idx >> 4, c4 = idx & 15;
    float4 wv = W4[idx];
    *reinterpret_cast<float4*>(&Ws[r*68 + c4*4]) = wv;
    float4 xv = X4[idx];
    *reinterpret_cast<float4*>(&xs[r*68 + c4*4]) = xv;
  }
  __syncthreads();

  float4 acc0 = make_float4(0.f,0.f,0.f,0.f);
  float4 acc1 = make_float4(0.f,0.f,0.f,0.f);
  float4 acc2 = make_float4(0.f,0.f,0.f,0.f);
  float4 acc3 = make_float4(0.f,0.f,0.f,0.f);
  const float* x0 = &xs[(ty*4+0)*68];
  const float* x1 = &xs[(ty*4+1)*68];
  const float* x2 = &xs[(ty*4+2)*68];
  const float* x3 = &xs[(ty*4+3)*68];
  #pragma unroll
  for(int k4=0; k4<16; k4++){
    float4 xa = *reinterpret_cast<const float4*>(&x0[k4*4]);
    float4 xb = *reinterpret_cast<const float4*>(&x1[k4*4]);
    float4 xc = *reinterpret_cast<const float4*>(&x2[k4*4]);
    float4 xd = *reinterpret_cast<const float4*>(&x3[k4*4]);
    #pragma unroll
    for(int j=0; j<4; j++){
      float4 b4 = *reinterpret_cast<const float4*>(&Ws[(k4*4+j)*68 + tx*4]);
      float a0 = f4c(xa,j), a1 = f4c(xb,j), a2 = f4c(xc,j), a3 = f4c(xd,j);
      acc0.x += a0*b4.x; acc0.y += a0*b4.y; acc0.z += a0*b4.z; acc0.w += a0*b4.w;
      acc1.x += a1*b4.x; acc1.y += a1*b4.y; acc1.z += a1*b4.z; acc1.w += a1*b4.w;
      acc2.x += a2*b4.x; acc2.y += a2*b4.y; acc2.z += a2*b4.z; acc2.w += a2*b4.w;
      acc3.x += a3*b4.x; acc3.y += a3*b4.y; acc3.z += a3*b4.z; acc3.w += a3*b4.w;
    }
  }

  int row0 = blockIdx.x*64 + ty*4;
  *reinterpret_cast<float4*>(&d_g[(row0+0)*64 + tx*4]) = acc0;
  *reinterpret_cast<float4*>(&d_g[(row0+1)*64 + tx*4]) = acc1;
  *reinterpret_cast<float4*>(&d_g[(row0+2)*64 + tx*4]) = acc2;
  *reinterpret_cast<float4*>(&d_g[(row0+3)*64 + tx*4]) = acc3;

  float4 av = *reinterpret_cast<const float4*>(&ati[tx*4]);
  float4 aw = *reinterpret_cast<const float4*>(&atj[tx*4]);
  sdi[(ty*4+0)*17+tx] = acc0.x*av.x+acc0.y*av.y+acc0.z*av.z+acc0.w*av.w;
  sdi[(ty*4+1)*17+tx] = acc1.x*av.x+acc1.y*av.y+acc1.z*av.z+acc1.w*av.w;
  sdi[(ty*4+2)*17+tx] = acc2.x*av.x+acc2.y*av.y+acc2.z*av.z+acc2.w*av.w;
  sdi[(ty*4+3)*17+tx] = acc3.x*av.x+acc3.y*av.y+acc3.z*av.z+acc3.w*av.w;
  sdj[(ty*4+0)*17+tx] = acc0.x*aw.x+acc0.y*aw.y+acc0.z*aw.z+acc0.w*aw.w;
  sdj[(ty*4+1)*17+tx] = acc1.x*aw.x+acc1.y*aw.y+acc1.z*aw.z+acc1.w*aw.w;
  sdj[(ty*4+2)*17+tx] = acc2.x*aw.x+acc2.y*aw.y+acc2.z*aw.z+acc2.w*aw.w;
  sdj[(ty*4+3)*17+tx] = acc3.x*aw.x+acc3.y*aw.y+acc3.z*aw.z+acc3.w*aw.w;
  __syncthreads();
  if(t < 64){
    float si = 0.f, sj = 0.f;
    #pragma unroll
    for(int m=0; m<16; m++){ si += sdi[t*17+m]; sj += sdj[t*17+m]; }
    int grow = blockIdx.x*64 + t;
    int node = grow & (Nn-1);
    d_si[grow] = si + d_eai[node];
    d_sj[grow] = sj + d_eaj[node];
  }
}

// ---- K4: one block per batch, packed-pair table gather (min MIO ops) ----
// dynamic smem floats: g[32768] | tab[512*11*4=22528] | si[512] | sj[512]
#define AT_G    0
#define AT_TAB  32768
#define AT_SI   (AT_TAB + 22528)   // 55296
#define AT_SJ   (AT_SI + 512)
#define AT_TOTAL_F (AT_SJ + 512)   // 56320 floats = 225280 bytes
#define ATTN_SMEM_BYTES (AT_TOTAL_F*4)

__global__ void __launch_bounds__(1024,1) k_attn(const float* __restrict__ gnn_bias){
  extern __shared__ float sm[];
  float* g_sm  = sm + AT_G;
  float* tab   = sm + AT_TAB;
  float* si_sm = sm + AT_SI;
  float* sj_sm = sm + AT_SJ;

  int t = threadIdx.x;               // 1024 threads
  int b = blockIdx.x;
  int lane = t & 31, w = t >> 5;
  int sub = lane & 15, half = lane >> 4;

  const float4* gg = reinterpret_cast<const float4*>(d_g) + b*8192;
  float4* g4st = reinterpret_cast<float4*>(g_sm);
  #pragma unroll
  for(int q=0; q<8; q++) g4st[q*1024+t] = gg[q*1024+t];
  if(t < 512){ sj_sm[t] = d_sj[b*512+t]; si_sm[t] = d_si[b*512+t]; }
  __syncthreads();

  // ---- phase 1: softmax -> packed (a_even, a_odd, addr_even, addr_odd) table ----
  for(int it=0; it<16; it++){
    int i = w*16 + it;
    int src = (lane < Kk) ? d_topk[i*Kk+lane] : i;   // lanes 20,21 -> self
    float z;
    if(lane <= Kk){
      z = si_sm[i] + sj_sm[src];
      z = (z > 0.f) ? z : 0.2f*z;
      if(lane < Kk && src == i) z = -INFINITY;
    } else z = -INFINITY;
    float m = warpMax(z);
    float e = (lane <= Kk) ? __expf(z - m) : 0.f;
    float s = warpSum(e);
    if(lane < 22){
      float a = e / s;                         // lane 21 -> 0
      float* tb = &tab[(i*11 + (lane>>1))*4 + (lane&1)];
      tb[0] = a;                               // .x or .y
      tb[2] = __int_as_float(src*16);          // .z or .w (float4 index)
    }
  }
  __syncthreads();

  // ---- phase 2: gather, 27 MIO ops/row ----
  const float4* g4  = reinterpret_cast<const float4*>(g_sm);
  const float4* tb4 = reinterpret_cast<const float4*>(tab);
  float4 bi4 = *reinterpret_cast<const float4*>(&gnn_bias[sub*4]);
  float4 ps = make_float4(0.f,0.f,0.f,0.f);
  float4 pq = make_float4(0.f,0.f,0.f,0.f);

  for(int it=0; it<16; it++){
    int i = w*16 + it;
    float4 acc = make_float4(0.f,0.f,0.f,0.f);
    #pragma unroll
    for(int p=0; p<11; p++){
      float4 tb = tb4[i*11 + p];               // broadcast LDS.128
      float a   = half ? tb.y : tb.x;
      int addr  = __float_as_int(half ? tb.w : tb.z);
      float4 v  = g4[addr + sub];              // LDS.128, 512B/warp-instr
      acc.x += a*v.x; acc.y += a*v.y; acc.z += a*v.z; acc.w += a*v.w;
    }
    acc.x += __shfl_xor_sync(0xffffffffu, acc.x, 16);
    acc.y += __shfl_xor_sync(0xffffffffu, acc.y, 16);
    acc.z += __shfl_xor_sync(0xffffffffu, acc.z, 16);
    acc.w += __shfl_xor_sync(0xffffffffu, acc.w, 16);
    if(half == 0){
      acc.x += bi4.x; acc.y += bi4.y; acc.z += bi4.z; acc.w += bi4.w;
      *reinterpret_cast<float4*>(&d_agg[(b*512+i)*64 + sub*4]) = acc;
      ps.x += acc.x; ps.y += acc.y; ps.z += acc.z; ps.w += acc.w;
      pq.x += acc.x*acc.x; pq.y += acc.y*acc.y; pq.z += acc.z*acc.z; pq.w += acc.w*acc.w;
    }
  }

  // ---- BN1 partials: alias scratch onto the (now dead) table region ----
  __syncthreads();
  float* rS = tab;            // 32*64
  float* rQ = tab + 2048;
  if(half == 0){
    int c0 = sub*4;
    rS[w*64+c0+0]=ps.x; rS[w*64+c0+1]=ps.y; rS[w*64+c0+2]=ps.z; rS[w*64+c0+3]=ps.w;
    rQ[w*64+c0+0]=pq.x; rQ[w*64+c0+1]=pq.y; rQ[w*64+c0+2]=pq.z; rQ[w*64+c0+3]=pq.w;
  }
  __syncthreads();
  if(t < 64){
    float S=0.f, Q=0.f;
    #pragma unroll
    for(int ww=0; ww<32; ww++){ S += rS[ww*64+t]; Q += rQ[ww*64+t]; }
    d_ps1[t*ATTN_BLOCKS + b] = S;
    d_pq1[t*ATTN_BLOCKS + b] = Q;
  }
}

// ---- K5: reduce BN partials -> scale/shift. block per channel. ----
__global__ void k_red(const float* __restrict__ ps, const float* __restrict__ pq,
                      int nblk, const float* __restrict__ gamma,
                      const float* __restrict__ beta,
                      float* __restrict__ scale, float* __restrict__ shift){
  __shared__ float shS[8], shQ[8];
  int c = blockIdx.x, t = threadIdx.x;
  float s = 0.f, q = 0.f;
  for(int idx=t; idx<nblk; idx+=256){
    s += ps[c*nblk+idx];
    q += pq[c*nblk+idx];
  }
  s = warpSum(s); q = warpSum(q);
  if((t&31)==0){ shS[t>>5]=s; shQ[t>>5]=q; }
  __syncthreads();
  if(t==0){
    float S=0.f, Q=0.f;
    #pragma unroll
    for(int ww=0; ww<8; ww++){ S+=shS[ww]; Q+=shQ[ww]; }
    float mu  = S * (1.0f/(float)BN);
    float var = Q * (1.0f/(float)BN) - mu*mu;
    float sc  = gamma[c] * rsqrtf(var + 1e-5f);
    scale[c] = sc;
    shift[c] = beta[c] - mu*sc;
  }
}

// ---- K6: BN2 stats only (h1 recomputed from agg, never stored) ----
__global__ void k_h1(const float* __restrict__ embed){
  __shared__ float shp[1024], shq2[1024];
  int t = threadIdx.x;
  int d0 = (t & 15) * 4;
  float4 sc1 = *reinterpret_cast<const float4*>(&d_scale1[d0]);
  float4 sh1 = *reinterpret_cast<const float4*>(&d_shift1[d0]);
  float4 psum = make_float4(0.f,0.f,0.f,0.f);
  float4 psq  = make_float4(0.f,0.f,0.f,0.f);
  #pragma unroll
  for(int q=0; q<4; q++){
    int i = blockIdx.x*1024 + q*256 + t;     // (i&15)==(t&15)
    int row  = i >> 4;
    int node = row & (Nn-1);
    float4 a  = reinterpret_cast<const float4*>(d_agg)[i];
    float4 em = reinterpret_cast<const float4*>(embed)[node*16 + (i&15)];
    float4 r;
    r.x = fmaxf(a.x*sc1.x+sh1.x, 0.f)*em.x;
    r.y = fmaxf(a.y*sc1.y+sh1.y, 0.f)*em.y;
    r.z = fmaxf(a.z*sc1.z+sh1.z, 0.f)*em.z;
    r.w = fmaxf(a.w*sc1.w+sh1.w, 0.f)*em.w;
    psum.x += r.x; psum.y += r.y; psum.z += r.z; psum.w += r.w;
    psq.x += r.x*r.x; psq.y += r.y*r.y; psq.z += r.z*r.z; psq.w += r.w*r.w;
  }
  shp[t*4+0]=psum.x; shp[t*4+1]=psum.y; shp[t*4+2]=psum.z; shp[t*4+3]=psum.w;
  shq2[t*4+0]=psq.x; shq2[t*4+1]=psq.y; shq2[t*4+2]=psq.z; shq2[t*4+3]=psq.w;
  __syncthreads();
  if(t < 64){
    int gi = t >> 2, comp = t & 3;
    float S=0.f, Q=0.f;
    #pragma unroll
    for(int m=0; m<16; m++){
      S += shp [(gi + m*16)*4 + comp];
      Q += shq2[(gi + m*16)*4 + comp];
    }
    d_ps2[t*H1_BLOCKS + blockIdx.x] = S;
    d_pq2[t*H1_BLOCKS + blockIdx.x] = Q;
  }
}

// ---- K7: out = relu(bn2(relu(bn1(agg))*embed)) @ out_W + out_b ----
__global__ void k_out(const float* __restrict__ embed,
                      const float* __restrict__ outW, const float* __restrict__ outB,
                      float* __restrict__ out){
  int lane = threadIdx.x & 31, w = threadIdx.x >> 5;
  int sub = lane & 15, half = lane >> 4;
  int row = blockIdx.x*16 + w*2 + half;
  int node = row & (Nn-1);
  float4 a   = *reinterpret_cast<const float4*>(&d_agg[row*64 + sub*4]);
  float4 em  = *reinterpret_cast<const float4*>(&embed[node*64 + sub*4]);
  float4 s1  = *reinterpret_cast<const float4*>(&d_scale1[sub*4]);
  float4 h1_ = *reinterpret_cast<const float4*>(&d_shift1[sub*4]);
  float4 s2  = *reinterpret_cast<const float4*>(&d_scale2[sub*4]);
  float4 h2_ = *reinterpret_cast<const float4*>(&d_shift2[sub*4]);
  float4 ow  = *reinterpret_cast<const float4*>(&outW[sub*4]);
  float hx = fmaxf(a.x*s1.x+h1_.x,0.f)*em.x;
  float hy = fmaxf(a.y*s1.y+h1_.y,0.f)*em.y;
  float hz = fmaxf(a.z*s1.z+h1_.z,0.f)*em.z;
  float hw = fmaxf(a.w*s1.w+h1_.w,0.f)*em.w;
  float p = fmaxf(hx*s2.x+h2_.x,0.f)*ow.x + fmaxf(hy*s2.y+h2_.y,0.f)*ow.y
          + fmaxf(hz*s2.z+h2_.z,0.f)*ow.z + fmaxf(hw*s2.w+h2_.w,0.f)*ow.w;
  #pragma unroll
  for(int o=8; o; o>>=1) p += __shfl_xor_sync(0xffffffffu, p, o);
  if(sub==0) out[row] = p + outB[0];
}

extern "C" void kernel_launch(void* const* d_in, const int* in_sizes, int n_in,
                              void* d_out, int out_size){
  int iData, iEmbed, iW, iAtI, iAtJ, iAemI, iAemJ, iBias, iG1, iB1, iG2, iB2, iOW, iOB;
  if(n_in >= 15 && in_sizes[1] == 2048){
    iData=0; iEmbed=2; iW=3; iAtI=4; iAtJ=5; iAemI=6; iAemJ=7; iBias=8;
    iG1=9; iB1=10; iG2=11; iB2=12; iOW=13; iOB=14;
  } else {
    iData=0; iEmbed=1; iW=2; iAtI=3; iAtJ=4; iAemI=5; iAemJ=6; iBias=7;
    iG1=8; iB1=9; iG2=10; iB2=11; iOW=12; iOB=13;
  }
  const float* data  = (const float*)d_in[iData];
  const float* embed = (const float*)d_in[iEmbed];
  const float* W     = (const float*)d_in[iW];
  const float* atI   = (const float*)d_in[iAtI];
  const float* atJ   = (const float*)d_in[iAtJ];
  const float* aemI  = (const float*)d_in[iAemI];
  const float* aemJ  = (const float*)d_in[iAemJ];
  const float* bias  = (const float*)d_in[iBias];
  const float* g1    = (const float*)d_in[iG1];
  const float* b1    = (const float*)d_in[iB1];
  const float* g2    = (const float*)d_in[iG2];
  const float* b2    = (const float*)d_in[iB2];
  const float* outW  = (const float*)d_in[iOW];
  const float* outB  = (const float*)d_in[iOB];
  float* out = (float*)d_out;

  float *sc1, *sh1, *sc2, *sh2, *ps1, *pq1, *ps2, *pq2;
  cudaGetSymbolAddress((void**)&sc1, d_scale1);
  cudaGetSymbolAddress((void**)&sh1, d_shift1);
  cudaGetSymbolAddress((void**)&sc2, d_scale2);
  cudaGetSymbolAddress((void**)&sh2, d_shift2);
  cudaGetSymbolAddress((void**)&ps1, d_ps1);
  cudaGetSymbolAddress((void**)&pq1, d_pq1);
  cudaGetSymbolAddress((void**)&ps2, d_ps2);
  cudaGetSymbolAddress((void**)&pq2, d_pq2);

  cudaFuncSetAttribute(k_attn, cudaFuncAttributeMaxDynamicSharedMemorySize, ATTN_SMEM_BYTES);

  k_embed<<<64, 256>>>(embed, aemI, aemJ);
  k_topk <<<64, 256>>>();
  k_gemm <<<BN/64, 256>>>(data, W, atI, atJ);
  k_attn <<<ATTN_BLOCKS, 1024, ATTN_SMEM_BYTES>>>(bias);
  k_red  <<<64, 256>>>(ps1, pq1, ATTN_BLOCKS, g1, b1, sc1, sh1);
  k_h1   <<<H1_BLOCKS, 256>>>(embed);
  k_red  <<<64, 256>>>(ps2, pq2, H1_BLOCKS, g2, b2, sc2, sh2);
  k_out  <<<BN/16, 256>>>(embed, outW, outB, out);
}

// round 9
// speedup vs baseline: 1.1303x; 1.0956x over previous
#include <cuda_runtime.h>
#include <cuda_fp16.h>
#include <math.h>

#define Bsz 128
#define Nn  512
#define Ff  64
#define Dd  64
#define Kk  20
#define BN  (Bsz*Nn)          // 65536
#define NELEM (BN*Dd)         // 4194304
#define AGRID 512             // 4 blocks per batch
#define H1_BLOCKS   1024

// ---------------- device scratch (no allocations allowed) ----------------
__device__ __half2 d_gh2[NELEM/2];        // g in fp16, [row][64]
__device__ float d_agg[NELEM];
__device__ float d_enorm[Nn*Dd];
__device__ float d_si[BN];
__device__ float d_sj[BN];
__device__ float d_eai[Nn];
__device__ float d_eaj[Nn];
__device__ int   d_topk[Nn*Kk];
__device__ float d_ps1[64*AGRID];         // channel-major BN1 partials
__device__ float d_pq1[64*AGRID];
__device__ float d_ps2[64*H1_BLOCKS];     // channel-major BN2 partials
__device__ float d_pq2[64*H1_BLOCKS];
__device__ float d_scale1[64], d_shift1[64], d_scale2[64], d_shift2[64];

__device__ __forceinline__ float warpSum(float v){
  #pragma unroll
  for(int o=16;o;o>>=1) v += __shfl_xor_sync(0xffffffffu, v, o);
  return v;
}
__device__ __forceinline__ float f4c(const float4& v, int j){
  return j==0 ? v.x : (j==1 ? v.y : (j==2 ? v.z : v.w));
}

// ---- K1: normalize embed rows, per-node embed-attention scalars ----
__global__ void k_embed(const float* __restrict__ embed,
                        const float* __restrict__ aemi,
                        const float* __restrict__ aemj){
  int gw   = (blockIdx.x*blockDim.x + threadIdx.x) >> 5;
  int lane = threadIdx.x & 31;
  if(gw >= Nn) return;
  float v0 = embed[gw*64+lane];
  float v1 = embed[gw*64+32+lane];
  float ss = warpSum(v0*v0 + v1*v1);
  float inv = 1.0f/(sqrtf(ss)+1e-12f);
  d_enorm[gw*64+lane]    = v0*inv;
  d_enorm[gw*64+32+lane] = v1*inv;
  float si = warpSum(v0*aemi[lane] + v1*aemi[lane+32]);
  float sj = warpSum(v0*aemj[lane] + v1*aemj[lane+32]);
  if(lane==0){ d_eai[gw]=si; d_eaj[gw]=sj; }
}

// ---- K2: warp-per-node topk, sims register-resident ----
__global__ void k_topk(){
  __shared__ float tile[64*68];
  __shared__ float srows[8*68];
  int t = threadIdx.x, w = t>>5, lane = t&31;
  int node = blockIdx.x*8 + w;

  if(t < 128){
    int r = t >> 4, c4 = t & 15;
    float4 v = reinterpret_cast<const float4*>(d_enorm)[(blockIdx.x*8 + r)*16 + c4];
    *reinterpret_cast<float4*>(&srows[r*68 + c4*4]) = v;
  }

  float sims[16];
  #pragma unroll
  for(int chunk=0; chunk<8; chunk++){
    __syncthreads();
    #pragma unroll
    for(int q=0; q<4; q++){
      int idx = t + q*256;
      int r = idx >> 4, c4 = idx & 15;
      float4 v = reinterpret_cast<const float4*>(d_enorm)[(chunk*64 + r)*16 + c4];
      *reinterpret_cast<float4*>(&tile[r*68 + c4*4]) = v;
    }
    __syncthreads();
    const float* sr = &srows[w*68];
    float a0 = 0.f, a1 = 0.f;
    #pragma unroll
    for(int kk=0; kk<64; kk+=4){
      float4 s4 = *reinterpret_cast<const float4*>(&sr[kk]);
      float4 e0 = *reinterpret_cast<const float4*>(&tile[lane*68+kk]);
      float4 e1 = *reinterpret_cast<const float4*>(&tile[(lane+32)*68+kk]);
      a0 += s4.x*e0.x + s4.y*e0.y + s4.z*e0.z + s4.w*e0.w;
      a1 += s4.x*e1.x + s4.y*e1.y + s4.z*e1.z + s4.w*e1.w;
    }
    sims[chunk*2]   = a0;
    sims[chunk*2+1] = a1;
  }

  for(int sel=0; sel<Kk; sel++){
    float bv = -INFINITY; int bj = 0x3fffffff;
    #pragma unroll
    for(int s=0; s<16; s++){
      float v = sims[s];
      int j = (s>>1)*64 + (s&1)*32 + lane;
      if(v > bv || (v == bv && j < bj)){ bv = v; bj = j; }
    }
    #pragma unroll
    for(int o=16; o; o>>=1){
      float ov = __shfl_xor_sync(0xffffffffu, bv, o);
      int   oj = __shfl_xor_sync(0xffffffffu, bj, o);
      if(ov > bv || (ov == bv && oj < bj)){ bv = ov; bj = oj; }
    }
    if(lane==0) d_topk[node*Kk+sel] = bj;
    int wslot = ((bj>>6)<<1) | ((bj>>5)&1);
    bool own = ((bj & 31) == lane);
    #pragma unroll
    for(int s=0; s<16; s++) if(own && s==wslot) sims[s] = -INFINITY;
  }
}

// ---- K3: g = x @ W_lin, register-tiled; writes g as fp16, + s_i/s_j ----
__global__ void k_gemm(const float* __restrict__ x, const float* __restrict__ W,
                       const float* __restrict__ ati, const float* __restrict__ atj){
  __shared__ float Ws[64*68];   // Ws[k*68 + col]
  __shared__ float xs[64*68];   // xs[row*68 + k]
  __shared__ float sdi[64*17], sdj[64*17];
  int t = threadIdx.x;
  int tx = t & 15, ty = t >> 4;

  const float4* W4 = reinterpret_cast<const float4*>(W);
  const float4* X4 = reinterpret_cast<const float4*>(x + blockIdx.x*64*64);
  #pragma unroll
  for(int q=0; q<4; q++){
    int idx = q*256 + t;
    int r = idx >> 4, c4 = idx & 15;
    float4 wv = W4[idx];
    *reinterpret_cast<float4*>(&Ws[r*68 + c4*4]) = wv;
    float4 xv = X4[idx];
    *reinterpret_cast<float4*>(&xs[r*68 + c4*4]) = xv;
  }
  __syncthreads();

  float4 acc0 = make_float4(0.f,0.f,0.f,0.f);
  float4 acc1 = make_float4(0.f,0.f,0.f,0.f);
  float4 acc2 = make_float4(0.f,0.f,0.f,0.f);
  float4 acc3 = make_float4(0.f,0.f,0.f,0.f);
  const float* x0 = &xs[(ty*4+0)*68];
  const float* x1 = &xs[(ty*4+1)*68];
  const float* x2 = &xs[(ty*4+2)*68];
  const float* x3 = &xs[(ty*4+3)*68];
  #pragma unroll
  for(int k4=0; k4<16; k4++){
    float4 xa = *reinterpret_cast<const float4*>(&x0[k4*4]);
    float4 xb = *reinterpret_cast<const float4*>(&x1[k4*4]);
    float4 xc = *reinterpret_cast<const float4*>(&x2[k4*4]);
    float4 xd = *reinterpret_cast<const float4*>(&x3[k4*4]);
    #pragma unroll
    for(int j=0; j<4; j++){
      float4 b4 = *reinterpret_cast<const float4*>(&Ws[(k4*4+j)*68 + tx*4]);
      float a0 = f4c(xa,j), a1 = f4c(xb,j), a2 = f4c(xc,j), a3 = f4c(xd,j);
      acc0.x += a0*b4.x; acc0.y += a0*b4.y; acc0.z += a0*b4.z; acc0.w += a0*b4.w;
      acc1.x += a1*b4.x; acc1.y += a1*b4.y; acc1.z += a1*b4.z; acc1.w += a1*b4.w;
      acc2.x += a2*b4.x; acc2.y += a2*b4.y; acc2.z += a2*b4.z; acc2.w += a2*b4.w;
      acc3.x += a3*b4.x; acc3.y += a3*b4.y; acc3.z += a3*b4.z; acc3.w += a3*b4.w;
    }
  }

  int row0 = blockIdx.x*64 + ty*4;
  uint2* gh = reinterpret_cast<uint2*>(d_gh2);
  {
    union { __half2 h[2]; uint2 u; } cv;
    cv.h[0] = __floats2half2_rn(acc0.x, acc0.y);
    cv.h[1] = __floats2half2_rn(acc0.z, acc0.w);
    gh[(row0+0)*16 + tx] = cv.u;
    cv.h[0] = __floats2half2_rn(acc1.x, acc1.y);
    cv.h[1] = __floats2half2_rn(acc1.z, acc1.w);
    gh[(row0+1)*16 + tx] = cv.u;
    cv.h[0] = __floats2half2_rn(acc2.x, acc2.y);
    cv.h[1] = __floats2half2_rn(acc2.z, acc2.w);
    gh[(row0+2)*16 + tx] = cv.u;
    cv.h[0] = __floats2half2_rn(acc3.x, acc3.y);
    cv.h[1] = __floats2half2_rn(acc3.z, acc3.w);
    gh[(row0+3)*16 + tx] = cv.u;
  }

  float4 av = *reinterpret_cast<const float4*>(&ati[tx*4]);
  float4 aw = *reinterpret_cast<const float4*>(&atj[tx*4]);
  sdi[(ty*4+0)*17+tx] = acc0.x*av.x+acc0.y*av.y+acc0.z*av.z+acc0.w*av.w;
  sdi[(ty*4+1)*17+tx] = acc1.x*av.x+acc1.y*av.y+acc1.z*av.z+acc1.w*av.w;
  sdi[(ty*4+2)*17+tx] = acc2.x*av.x+acc2.y*av.y+acc2.z*av.z+acc2.w*av.w;
  sdi[(ty*4+3)*17+tx] = acc3.x*av.x+acc3.y*av.y+acc3.z*av.z+acc3.w*av.w;
  sdj[(ty*4+0)*17+tx] = acc0.x*aw.x+acc0.y*aw.y+acc0.z*aw.z+acc0.w*aw.w;
  sdj[(ty*4+1)*17+tx] = acc1.x*aw.x+acc1.y*aw.y+acc1.z*aw.z+acc1.w*aw.w;
  sdj[(ty*4+2)*17+tx] = acc2.x*aw.x+acc2.y*aw.y+acc2.z*aw.z+acc2.w*aw.w;
  sdj[(ty*4+3)*17+tx] = acc3.x*aw.x+acc3.y*aw.y+acc3.z*aw.z+acc3.w*aw.w;
  __syncthreads();
  if(t < 64){
    float si = 0.f, sj = 0.f;
    #pragma unroll
    for(int m=0; m<16; m++){ si += sdi[t*17+m]; sj += sdj[t*17+m]; }
    int grow = blockIdx.x*64 + t;
    int node = grow & (Nn-1);
    d_si[grow] = si + d_eai[node];
    d_sj[grow] = sj + d_eaj[node];
  }
}

// ---- K4: 4 blocks/batch, 512 threads; fp16 g slice in smem (68KB) ----
// Per edge: 1 packed SHFL + 1 LDS.32(half2) + cvt + 2 FFMA. No combine.
#define ATTN_SMEM_FLOATS (16384 + 512 + 128)   // gh(64KB) + sj + si
#define ATTN_SMEM_BYTES  (ATTN_SMEM_FLOATS*4)

__global__ void __launch_bounds__(512,3) k_attn(const float* __restrict__ gnn_bias){
  extern __shared__ float sm[];
  __half2* gh_sm = reinterpret_cast<__half2*>(sm);   // [src*32 + lane]
  float* sj_sm = sm + 16384;   // 512
  float* si_sm = sm + 16896;   // 128 (this block's rows)

  int t = threadIdx.x, lane = t & 31, w = t >> 5;
  int b  = blockIdx.x >> 2;
  int row0 = (blockIdx.x & 3) * 128;

  // load fp16 g slice (64KB) + scores
  const uint4* s4 = reinterpret_cast<const uint4*>(d_gh2 + (size_t)b*16384);
  uint4* dst4 = reinterpret_cast<uint4*>(sm);
  #pragma unroll
  for(int q=0; q<8; q++) dst4[q*512+t] = s4[q*512+t];
  sj_sm[t] = d_sj[b*512+t];
  if(t < 128) si_sm[t] = d_si[b*512 + row0 + t];
  __syncthreads();

  float2 bi2 = reinterpret_cast<const float2*>(gnn_bias)[lane];
  float2 ps = make_float2(0.f,0.f), pq = make_float2(0.f,0.f);

  for(int it=0; it<8; it++){
    int il = w*8 + it;            // local row 0..127
    int i  = row0 + il;           // node in batch
    unsigned packed;
    {
      int src = (lane < Kk) ? d_topk[i*Kk + lane] : i;  // lane 20 -> self
      float z;
      if(lane <= Kk){
        z = si_sm[il] + sj_sm[src];
        z = (z > 0.f) ? z : 0.2f*z;
        if(lane < Kk && src == i) z = -INFINITY;
      } else z = -INFINITY;
      float e = (lane <= Kk) ? __expf(z) : 0.f;   // no max-subtract (z bounded)
      float s = warpSum(e);
      float a = e / s;
      packed = (__float_as_uint(a) & 0xFFFFFE00u) | (unsigned)src;
    }
    float2 acc = make_float2(0.f,0.f);
    #pragma unroll
    for(int e=0; e<=Kk; e++){
      unsigned pk = __shfl_sync(0xffffffffu, packed, e);
      float a  = __uint_as_float(pk & 0xFFFFFE00u);
      int srow = (int)(pk & 511u);
      float2 v = __half22float2(gh_sm[srow*32 + lane]);
      acc.x += a*v.x; acc.y += a*v.y;
    }
    acc.x += bi2.x; acc.y += bi2.y;
    reinterpret_cast<float2*>(&d_agg[(size_t)(b*512+i)*64])[lane] = acc;
    ps.x += acc.x; ps.y += acc.y;
    pq.x += acc.x*acc.x; pq.y += acc.y*acc.y;
  }

  // BN1 partials — alias scratch onto gh region (all gathers done)
  __syncthreads();
  float* rS = sm;          // 16*64
  float* rQ = sm + 1024;   // 16*64
  rS[w*64 + lane*2]   = ps.x;
  rS[w*64 + lane*2+1] = ps.y;
  rQ[w*64 + lane*2]   = pq.x;
  rQ[w*64 + lane*2+1] = pq.y;
  __syncthreads();
  if(t < 64){
    float S=0.f, Q=0.f;
    #pragma unroll
    for(int ww=0; ww<16; ww++){ S += rS[ww*64+t]; Q += rQ[ww*64+t]; }
    d_ps1[t*AGRID + blockIdx.x] = S;
    d_pq1[t*AGRID + blockIdx.x] = Q;
  }
}

// ---- K5: reduce BN partials -> scale/shift. block per channel. ----
__global__ void k_red(const float* __restrict__ ps, const float* __restrict__ pq,
                      int nblk, const float* __restrict__ gamma,
                      const float* __restrict__ beta,
                      float* __restrict__ scale, float* __restrict__ shift){
  __shared__ float shS[8], shQ[8];
  int c = blockIdx.x, t = threadIdx.x;
  float s = 0.f, q = 0.f;
  for(int idx=t; idx<nblk; idx+=256){
    s += ps[c*nblk+idx];
    q += pq[c*nblk+idx];
  }
  s = warpSum(s); q = warpSum(q);
  if((t&31)==0){ shS[t>>5]=s; shQ[t>>5]=q; }
  __syncthreads();
  if(t==0){
    float S=0.f, Q=0.f;
    #pragma unroll
    for(int ww=0; ww<8; ww++){ S+=shS[ww]; Q+=shQ[ww]; }
    float mu  = S * (1.0f/(float)BN);
    float var = Q * (1.0f/(float)BN) - mu*mu;
    float sc  = gamma[c] * rsqrtf(var + 1e-5f);
    scale[c] = sc;
    shift[c] = beta[c] - mu*sc;
  }
}

// ---- K6: BN2 stats only (h1 recomputed from agg, never stored) ----
__global__ void k_h1(const float* __restrict__ embed){
  __shared__ float shp[1024], shq2[1024];
  int t = threadIdx.x;
  int d0 = (t & 15) * 4;
  float4 sc1 = *reinterpret_cast<const float4*>(&d_scale1[d0]);
  float4 sh1 = *reinterpret_cast<const float4*>(&d_shift1[d0]);
  float4 psum = make_float4(0.f,0.f,0.f,0.f);
  float4 psq  = make_float4(0.f,0.f,0.f,0.f);
  #pragma unroll
  for(int q=0; q<4; q++){
    int i = blockIdx.x*1024 + q*256 + t;     // (i&15)==(t&15)
    int row  = i >> 4;
    int node = row & (Nn-1);
    float4 a  = reinterpret_cast<const float4*>(d_agg)[i];
    float4 em = reinterpret_cast<const float4*>(embed)[node*16 + (i&15)];
    float4 r;
    r.x = fmaxf(a.x*sc1.x+sh1.x, 0.f)*em.x;
    r.y = fmaxf(a.y*sc1.y+sh1.y, 0.f)*em.y;
    r.z = fmaxf(a.z*sc1.z+sh1.z, 0.f)*em.z;
    r.w = fmaxf(a.w*sc1.w+sh1.w, 0.f)*em.w;
    psum.x += r.x; psum.y += r.y; psum.z += r.z; psum.w += r.w;
    psq.x += r.x*r.x; psq.y += r.y*r.y; psq.z += r.z*r.z; psq.w += r.w*r.w;
  }
  shp[t*4+0]=psum.x; shp[t*4+1]=psum.y; shp[t*4+2]=psum.z; shp[t*4+3]=psum.w;
  shq2[t*4+0]=psq.x; shq2[t*4+1]=psq.y; shq2[t*4+2]=psq.z; shq2[t*4+3]=psq.w;
  __syncthreads();
  if(t < 64){
    int gi = t >> 2, comp = t & 3;
    float S=0.f, Q=0.f;
    #pragma unroll
    for(int m=0; m<16; m++){
      S += shp [(gi + m*16)*4 + comp];
      Q += shq2[(gi + m*16)*4 + comp];
    }
    d_ps2[t*H1_BLOCKS + blockIdx.x] = S;
    d_pq2[t*H1_BLOCKS + blockIdx.x] = Q;
  }
}

// ---- K7: out = relu(bn2(relu(bn1(agg))*embed)) @ out_W + out_b ----
__global__ void k_out(const float* __restrict__ embed,
                      const float* __restrict__ outW, const float* __restrict__ outB,
                      float* __restrict__ out){
  int lane = threadIdx.x & 31, w = threadIdx.x >> 5;
  int sub = lane & 15, half = lane >> 4;
  int row = blockIdx.x*16 + w*2 + half;
  int node = row & (Nn-1);
  float4 a   = *reinterpret_cast<const float4*>(&d_agg[row*64 + sub*4]);
  float4 em  = *reinterpret_cast<const float4*>(&embed[node*64 + sub*4]);
  float4 s1  = *reinterpret_cast<const float4*>(&d_scale1[sub*4]);
  float4 h1_ = *reinterpret_cast<const float4*>(&d_shift1[sub*4]);
  float4 s2  = *reinterpret_cast<const float4*>(&d_scale2[sub*4]);
  float4 h2_ = *reinterpret_cast<const float4*>(&d_shift2[sub*4]);
  float4 ow  = *reinterpret_cast<const float4*>(&outW[sub*4]);
  float hx = fmaxf(a.x*s1.x+h1_.x,0.f)*em.x;
  float hy = fmaxf(a.y*s1.y+h1_.y,0.f)*em.y;
  float hz = fmaxf(a.z*s1.z+h1_.z,0.f)*em.z;
  float hw = fmaxf(a.w*s1.w+h1_.w,0.f)*em.w;
  float p = fmaxf(hx*s2.x+h2_.x,0.f)*ow.x + fmaxf(hy*s2.y+h2_.y,0.f)*ow.y
          + fmaxf(hz*s2.z+h2_.z,0.f)*ow.z + fmaxf(hw*s2.w+h2_.w,0.f)*ow.w;
  #pragma unroll
  for(int o=8; o; o>>=1) p += __shfl_xor_sync(0xffffffffu, p, o);
  if(sub==0) out[row] = p + outB[0];
}

extern "C" void kernel_launch(void* const* d_in, const int* in_sizes, int n_in,
                              void* d_out, int out_size){
  int iData, iEmbed, iW, iAtI, iAtJ, iAemI, iAemJ, iBias, iG1, iB1, iG2, iB2, iOW, iOB;
  if(n_in >= 15 && in_sizes[1] == 2048){
    iData=0; iEmbed=2; iW=3; iAtI=4; iAtJ=5; iAemI=6; iAemJ=7; iBias=8;
    iG1=9; iB1=10; iG2=11; iB2=12; iOW=13; iOB=14;
  } else {
    iData=0; iEmbed=1; iW=2; iAtI=3; iAtJ=4; iAemI=5; iAemJ=6; iBias=7;
    iG1=8; iB1=9; iG2=10; iB2=11; iOW=12; iOB=13;
  }
  const float* data  = (const float*)d_in[iData];
  const float* embed = (const float*)d_in[iEmbed];
  const float* W     = (const float*)d_in[iW];
  const float* atI   = (const float*)d_in[iAtI];
  const float* atJ   = (const float*)d_in[iAtJ];
  const float* aemI  = (const float*)d_in[iAemI];
  const float* aemJ  = (const float*)d_in[iAemJ];
  const float* bias  = (const float*)d_in[iBias];
  const float* g1    = (const float*)d_in[iG1];
  const float* b1    = (const float*)d_in[iB1];
  const float* g2    = (const float*)d_in[iG2];
  const float* b2    = (const float*)d_in[iB2];
  const float* outW  = (const float*)d_in[iOW];
  const float* outB  = (const float*)d_in[iOB];
  float* out = (float*)d_out;

  float *sc1, *sh1, *sc2, *sh2, *ps1, *pq1, *ps2, *pq2;
  cudaGetSymbolAddress((void**)&sc1, d_scale1);
  cudaGetSymbolAddress((void**)&sh1, d_shift1);
  cudaGetSymbolAddress((void**)&sc2, d_scale2);
  cudaGetSymbolAddress((void**)&sh2, d_shift2);
  cudaGetSymbolAddress((void**)&ps1, d_ps1);
  cudaGetSymbolAddress((void**)&pq1, d_pq1);
  cudaGetSymbolAddress((void**)&ps2, d_ps2);
  cudaGetSymbolAddress((void**)&pq2, d_pq2);

  cudaFuncSetAttribute(k_attn, cudaFuncAttributeMaxDynamicSharedMemorySize, ATTN_SMEM_BYTES);

  k_embed<<<64, 256>>>(embed, aemI, aemJ);
  k_topk <<<64, 256>>>();
  k_gemm <<<BN/64, 256>>>(data, W, atI, atJ);
  k_attn <<<AGRID, 512, ATTN_SMEM_BYTES>>>(bias);
  k_red  <<<64, 256>>>(ps1, pq1, AGRID, g1, b1, sc1, sh1);
  k_h1   <<<H1_BLOCKS, 256>>>(embed);
  k_red  <<<64, 256>>>(ps2, pq2, H1_BLOCKS, g2, b2, sc2, sh2);
  k_out  <<<BN/16, 256>>>(embed, outW, outB, out);
}

// round 10
// speedup vs baseline: 1.1835x; 1.0471x over previous
#include <cuda_runtime.h>
#include <cuda_fp16.h>
#include <mma.h>
#include <math.h>

using namespace nvcuda;

#define Bsz 128
#define Nn  512
#define Ff  64
#define Dd  64
#define Kk  20
#define BN  (Bsz*Nn)          // 65536
#define NELEM (BN*Dd)         // 4194304
#define AGRID 512             // 4 blocks per batch
#define H1_BLOCKS   1024

// ---------------- device scratch (no allocations allowed) ----------------
__device__ __half2 d_gh2[NELEM/2];        // g in fp16, [row][64]
__device__ float d_agg[NELEM];
__device__ float d_enorm[Nn*Dd];
__device__ float d_si[BN];
__device__ float d_sj[BN];
__device__ float d_eai[Nn];
__device__ float d_eaj[Nn];
__device__ int   d_topk[Nn*Kk];
__device__ float d_ps1[64*AGRID];         // channel-major BN1 partials
__device__ float d_pq1[64*AGRID];
__device__ float d_ps2[64*H1_BLOCKS];     // channel-major BN2 partials
__device__ float d_pq2[64*H1_BLOCKS];
__device__ float d_scale1[64], d_shift1[64], d_scale2[64], d_shift2[64];

__device__ __forceinline__ float warpSum(float v){
  #pragma unroll
  for(int o=16;o;o>>=1) v += __shfl_xor_sync(0xffffffffu, v, o);
  return v;
}

// ---- K1: normalize embed rows, per-node embed-attention scalars ----
__global__ void k_embed(const float* __restrict__ embed,
                        const float* __restrict__ aemi,
                        const float* __restrict__ aemj){
  int gw   = (blockIdx.x*blockDim.x + threadIdx.x) >> 5;
  int lane = threadIdx.x & 31;
  if(gw >= Nn) return;
  float v0 = embed[gw*64+lane];
  float v1 = embed[gw*64+32+lane];
  float ss = warpSum(v0*v0 + v1*v1);
  float inv = 1.0f/(sqrtf(ss)+1e-12f);
  d_enorm[gw*64+lane]    = v0*inv;
  d_enorm[gw*64+32+lane] = v1*inv;
  float si = warpSum(v0*aemi[lane] + v1*aemi[lane+32]);
  float sj = warpSum(v0*aemj[lane] + v1*aemj[lane+32]);
  if(lane==0){ d_eai[gw]=si; d_eaj[gw]=sj; }
}

// ---- K2: warp-per-node topk, sims register-resident ----
__global__ void k_topk(){
  __shared__ float tile[64*68];
  __shared__ float srows[8*68];
  int t = threadIdx.x, w = t>>5, lane = t&31;
  int node = blockIdx.x*8 + w;

  if(t < 128){
    int r = t >> 4, c4 = t & 15;
    float4 v = reinterpret_cast<const float4*>(d_enorm)[(blockIdx.x*8 + r)*16 + c4];
    *reinterpret_cast<float4*>(&srows[r*68 + c4*4]) = v;
  }

  float sims[16];
  #pragma unroll
  for(int chunk=0; chunk<8; chunk++){
    __syncthreads();
    #pragma unroll
    for(int q=0; q<4; q++){
      int idx = t + q*256;
      int r = idx >> 4, c4 = idx & 15;
      float4 v = reinterpret_cast<const float4*>(d_enorm)[(chunk*64 + r)*16 + c4];
      *reinterpret_cast<float4*>(&tile[r*68 + c4*4]) = v;
    }
    __syncthreads();
    const float* sr = &srows[w*68];
    float a0 = 0.f, a1 = 0.f;
    #pragma unroll
    for(int kk=0; kk<64; kk+=4){
      float4 s4 = *reinterpret_cast<const float4*>(&sr[kk]);
      float4 e0 = *reinterpret_cast<const float4*>(&tile[lane*68+kk]);
      float4 e1 = *reinterpret_cast<const float4*>(&tile[(lane+32)*68+kk]);
      a0 += s4.x*e0.x + s4.y*e0.y + s4.z*e0.z + s4.w*e0.w;
      a1 += s4.x*e1.x + s4.y*e1.y + s4.z*e1.z + s4.w*e1.w;
    }
    sims[chunk*2]   = a0;
    sims[chunk*2+1] = a1;
  }

  for(int sel=0; sel<Kk; sel++){
    float bv = -INFINITY; int bj = 0x3fffffff;
    #pragma unroll
    for(int s=0; s<16; s++){
      float v = sims[s];
      int j = (s>>1)*64 + (s&1)*32 + lane;
      if(v > bv || (v == bv && j < bj)){ bv = v; bj = j; }
    }
    #pragma unroll
    for(int o=16; o; o>>=1){
      float ov = __shfl_xor_sync(0xffffffffu, bv, o);
      int   oj = __shfl_xor_sync(0xffffffffu, bj, o);
      if(ov > bv || (ov == bv && oj < bj)){ bv = ov; bj = oj; }
    }
    if(lane==0) d_topk[node*Kk+sel] = bj;
    int wslot = ((bj>>6)<<1) | ((bj>>5)&1);
    bool own = ((bj & 31) == lane);
    #pragma unroll
    for(int s=0; s<16; s++) if(own && s==wslot) sims[s] = -INFINITY;
  }
}

// ---- K3: g = x @ W_lin via WMMA (half inputs, fp32 accum), + s_i/s_j ----
// 512 blocks x 256 threads; block computes 128 rows.
// dyn smem: Xh[128*72 half]=18432B | Wh[64*72 half]=9216B | Cs[128*68 f32]=34816B
#define GS_XH 0
#define GS_WH 18432
#define GS_CS 27648
#define GEMM_SMEM (27648 + 128*68*4)   // 62464

__global__ void __launch_bounds__(256,3) k_gemm(const float* __restrict__ x,
                       const float* __restrict__ W,
                       const float* __restrict__ ati, const float* __restrict__ atj){
  extern __shared__ char gsm[];
  __half* Xh = reinterpret_cast<__half*>(gsm + GS_XH);
  __half* Wh = reinterpret_cast<__half*>(gsm + GS_WH);
  float*  Cs = reinterpret_cast<float*>(gsm + GS_CS);
  __shared__ float s_si[128][2], s_sj[128][2];

  int t = threadIdx.x;

  // W: 4096 floats -> half (2048 float2)
  const float2* W2 = reinterpret_cast<const float2*>(W);
  #pragma unroll
  for(int q=0; q<8; q++){
    int idx = q*256 + t;
    float2 wv = W2[idx];
    int r = idx >> 5, c2 = idx & 31;
    reinterpret_cast<__half2*>(Wh + r*72)[c2] = __floats2half2_rn(wv.x, wv.y);
  }
  // x rows: 128*64 floats (4096 float2)
  const float2* X2 = reinterpret_cast<const float2*>(x + (size_t)blockIdx.x*128*64);
  #pragma unroll
  for(int q=0; q<16; q++){
    int idx = q*256 + t;
    float2 xv = X2[idx];
    int r = idx >> 5, c2 = idx & 31;
    reinterpret_cast<__half2*>(Xh + r*72)[c2] = __floats2half2_rn(xv.x, xv.y);
  }
  __syncthreads();

  int w = t >> 5;   // 8 warps; warp w -> rows [w*16, w*16+16)
  wmma::fragment<wmma::accumulator,16,16,16,float> acc[4];
  #pragma unroll
  for(int n=0; n<4; n++) wmma::fill_fragment(acc[n], 0.0f);
  #pragma unroll
  for(int k=0; k<4; k++){
    wmma::fragment<wmma::matrix_a,16,16,16,__half,wmma::row_major> fa;
    wmma::load_matrix_sync(fa, Xh + (w*16)*72 + k*16, 72);
    #pragma unroll
    for(int n=0; n<4; n++){
      wmma::fragment<wmma::matrix_b,16,16,16,__half,wmma::row_major> fb;
      wmma::load_matrix_sync(fb, Wh + (k*16)*72 + n*16, 72);
      wmma::mma_sync(acc[n], fa, fb, acc[n]);
    }
  }
  #pragma unroll
  for(int n=0; n<4; n++)
    wmma::store_matrix_sync(Cs + (w*16)*68 + n*16, acc[n], 68, wmma::mem_row_major);
  __syncthreads();

  // si/sj + fp16 g store. thread t: row = t>>1, cols [hf*32, hf*32+32)
  int row = t >> 1, hf = t & 1;
  const float* crow = Cs + row*68 + hf*32;
  float si = 0.f, sj = 0.f;
  union { __half2 h2[16]; uint4 u4[4]; } cv;
  #pragma unroll
  for(int q=0; q<8; q++){
    float4 c4 = *reinterpret_cast<const float4*>(crow + q*4);
    float4 av = *reinterpret_cast<const float4*>(ati + hf*32 + q*4);
    float4 aw = *reinterpret_cast<const float4*>(atj + hf*32 + q*4);
    si += c4.x*av.x + c4.y*av.y + c4.z*av.z + c4.w*av.w;
    sj += c4.x*aw.x + c4.y*aw.y + c4.z*aw.z + c4.w*aw.w;
    cv.h2[q*2]   = __floats2half2_rn(c4.x, c4.y);
    cv.h2[q*2+1] = __floats2half2_rn(c4.z, c4.w);
  }
  uint4* ghp = reinterpret_cast<uint4*>(d_gh2);
  int grow = blockIdx.x*128 + row;
  #pragma unroll
  for(int q=0; q<4; q++) ghp[(size_t)grow*8 + hf*4 + q] = cv.u4[q];
  s_si[row][hf] = si; s_sj[row][hf] = sj;
  __syncthreads();
  if(t < 128){
    int gr = blockIdx.x*128 + t;
    int node = gr & (Nn-1);
    d_si[gr] = s_si[t][0] + s_si[t][1] + d_eai[node];
    d_sj[gr] = s_sj[t][0] + s_sj[t][1] + d_eaj[node];
  }
}

// ---- K4: 4 blocks/batch, 512 threads; fp16 g slice in smem (68KB) ----
#define ATTN_SMEM_FLOATS (16384 + 512 + 128)   // gh(64KB) + sj + si
#define ATTN_SMEM_BYTES  (ATTN_SMEM_FLOATS*4)

__global__ void __launch_bounds__(512,3) k_attn(const float* __restrict__ gnn_bias){
  extern __shared__ float sm[];
  __half2* gh_sm = reinterpret_cast<__half2*>(sm);   // [src*32 + lane]
  float* sj_sm = sm + 16384;   // 512
  float* si_sm = sm + 16896;   // 128 (this block's rows)

  int t = threadIdx.x, lane = t & 31, w = t >> 5;
  int b  = blockIdx.x >> 2;
  int row0 = (blockIdx.x & 3) * 128;

  const uint4* s4 = reinterpret_cast<const uint4*>(d_gh2 + (size_t)b*16384);
  uint4* dst4 = reinterpret_cast<uint4*>(sm);
  #pragma unroll
  for(int q=0; q<8; q++) dst4[q*512+t] = s4[q*512+t];
  sj_sm[t] = d_sj[b*512+t];
  if(t < 128) si_sm[t] = d_si[b*512 + row0 + t];
  __syncthreads();

  float2 bi2 = reinterpret_cast<const float2*>(gnn_bias)[lane];
  float2 ps = make_float2(0.f,0.f), pq = make_float2(0.f,0.f);

  for(int it=0; it<8; it++){
    int il = w*8 + it;            // local row 0..127
    int i  = row0 + il;           // node in batch
    unsigned packed;
    {
      int src = (lane < Kk) ? d_topk[i*Kk + lane] : i;  // lane 20 -> self
      float z;
      if(lane <= Kk){
        z = si_sm[il] + sj_sm[src];
        z = (z > 0.f) ? z : 0.2f*z;
        if(lane < Kk && src == i) z = -INFINITY;
      } else z = -INFINITY;
      float e = (lane <= Kk) ? __expf(z) : 0.f;   // no max-subtract (z bounded)
      float s = warpSum(e);
      float a = e / s;
      packed = (__float_as_uint(a) & 0xFFFFFE00u) | (unsigned)src;
    }
    float2 acc = make_float2(0.f,0.f);
    #pragma unroll
    for(int e=0; e<=Kk; e++){
      unsigned pk = __shfl_sync(0xffffffffu, packed, e);
      float a  = __uint_as_float(pk & 0xFFFFFE00u);
      int srow = (int)(pk & 511u);
      float2 v = __half22float2(gh_sm[srow*32 + lane]);
      acc.x += a*v.x; acc.y += a*v.y;
    }
    acc.x += bi2.x; acc.y += bi2.y;
    reinterpret_cast<float2*>(&d_agg[(size_t)(b*512+i)*64])[lane] = acc;
    ps.x += acc.x; ps.y += acc.y;
    pq.x += acc.x*acc.x; pq.y += acc.y*acc.y;
  }

  __syncthreads();
  float* rS = sm;          // 16*64
  float* rQ = sm + 1024;   // 16*64
  rS[w*64 + lane*2]   = ps.x;
  rS[w*64 + lane*2+1] = ps.y;
  rQ[w*64 + lane*2]   = pq.x;
  rQ[w*64 + lane*2+1] = pq.y;
  __syncthreads();
  if(t < 64){
    float S=0.f, Q=0.f;
    #pragma unroll
    for(int ww=0; ww<16; ww++){ S += rS[ww*64+t]; Q += rQ[ww*64+t]; }
    d_ps1[t*AGRID + blockIdx.x] = S;
    d_pq1[t*AGRID + blockIdx.x] = Q;
  }
}

// ---- K5: reduce BN partials -> scale/shift. block per channel. ----
__global__ void k_red(const float* __restrict__ ps, const float* __restrict__ pq,
                      int nblk, const float* __restrict__ gamma,
                      const float* __restrict__ beta,
                      float* __restrict__ scale, float* __restrict__ shift){
  __shared__ float shS[8], shQ[8];
  int c = blockIdx.x, t = threadIdx.x;
  float s = 0.f, q = 0.f;
  for(int idx=t; idx<nblk; idx+=256){
    s += ps[c*nblk+idx];
    q += pq[c*nblk+idx];
  }
  s = warpSum(s); q = warpSum(q);
  if((t&31)==0){ shS[t>>5]=s; shQ[t>>5]=q; }
  __syncthreads();
  if(t==0){
    float S=0.f, Q=0.f;
    #pragma unroll
    for(int ww=0; ww<8; ww++){ S+=shS[ww]; Q+=shQ[ww]; }
    float mu  = S * (1.0f/(float)BN);
    float var = Q * (1.0f/(float)BN) - mu*mu;
    float sc  = gamma[c] * rsqrtf(var + 1e-5f);
    scale[c] = sc;
    shift[c] = beta[c] - mu*sc;
  }
}

// ---- K6: BN2 stats only (h1 recomputed from agg, never stored) ----
__global__ void k_h1(const float* __restrict__ embed){
  __shared__ float shp[1024], shq2[1024];
  int t = threadIdx.x;
  int d0 = (t & 15) * 4;
  float4 sc1 = *reinterpret_cast<const float4*>(&d_scale1[d0]);
  float4 sh1 = *reinterpret_cast<const float4*>(&d_shift1[d0]);
  float4 psum = make_float4(0.f,0.f,0.f,0.f);
  float4 psq  = make_float4(0.f,0.f,0.f,0.f);
  #pragma unroll
  for(int q=0; q<4; q++){
    int i = blockIdx.x*1024 + q*256 + t;     // (i&15)==(t&15)
    int row  = i >> 4;
    int node = row & (Nn-1);
    float4 a  = reinterpret_cast<const float4*>(d_agg)[i];
    float4 em = reinterpret_cast<const float4*>(embed)[node*16 + (i&15)];
    float4 r;
    r.x = fmaxf(a.x*sc1.x+sh1.x, 0.f)*em.x;
    r.y = fmaxf(a.y*sc1.y+sh1.y, 0.f)*em.y;
    r.z = fmaxf(a.z*sc1.z+sh1.z, 0.f)*em.z;
    r.w = fmaxf(a.w*sc1.w+sh1.w, 0.f)*em.w;
    psum.x += r.x; psum.y += r.y; psum.z += r.z; psum.w += r.w;
    psq.x += r.x*r.x; psq.y += r.y*r.y; psq.z += r.z*r.z; psq.w += r.w*r.w;
  }
  shp[t*4+0]=psum.x; shp[t*4+1]=psum.y; shp[t*4+2]=psum.z; shp[t*4+3]=psum.w;
  shq2[t*4+0]=psq.x; shq2[t*4+1]=psq.y; shq2[t*4+2]=psq.z; shq2[t*4+3]=psq.w;
  __syncthreads();
  if(t < 64){
    int gi = t >> 2, comp = t & 3;
    float S=0.f, Q=0.f;
    #pragma unroll
    for(int m=0; m<16; m++){
      S += shp [(gi + m*16)*4 + comp];
      Q += shq2[(gi + m*16)*4 + comp];
    }
    d_ps2[t*H1_BLOCKS + blockIdx.x] = S;
    d_pq2[t*H1_BLOCKS + blockIdx.x] = Q;
  }
}

// ---- K7: out = relu(bn2(relu(bn1(agg))*embed)) @ out_W + out_b ----
__global__ void k_out(const float* __restrict__ embed,
                      const float* __restrict__ outW, const float* __restrict__ outB,
                      float* __restrict__ out){
  int lane = threadIdx.x & 31, w = threadIdx.x >> 5;
  int sub = lane & 15, half = lane >> 4;
  int row = blockIdx.x*16 + w*2 + half;
  int node = row & (Nn-1);
  float4 a   = *reinterpret_cast<const float4*>(&d_agg[row*64 + sub*4]);
  float4 em  = *reinterpret_cast<const float4*>(&embed[node*64 + sub*4]);
  float4 s1  = *reinterpret_cast<const float4*>(&d_scale1[sub*4]);
  float4 h1_ = *reinterpret_cast<const float4*>(&d_shift1[sub*4]);
  float4 s2  = *reinterpret_cast<const float4*>(&d_scale2[sub*4]);
  float4 h2_ = *reinterpret_cast<const float4*>(&d_shift2[sub*4]);
  float4 ow  = *reinterpret_cast<const float4*>(&outW[sub*4]);
  float hx = fmaxf(a.x*s1.x+h1_.x,0.f)*em.x;
  float hy = fmaxf(a.y*s1.y+h1_.y,0.f)*em.y;
  float hz = fmaxf(a.z*s1.z+h1_.z,0.f)*em.z;
  float hw = fmaxf(a.w*s1.w+h1_.w,0.f)*em.w;
  float p = fmaxf(hx*s2.x+h2_.x,0.f)*ow.x + fmaxf(hy*s2.y+h2_.y,0.f)*ow.y
          + fmaxf(hz*s2.z+h2_.z,0.f)*ow.z + fmaxf(hw*s2.w+h2_.w,0.f)*ow.w;
  #pragma unroll
  for(int o=8; o; o>>=1) p += __shfl_xor_sync(0xffffffffu, p, o);
  if(sub==0) out[row] = p + outB[0];
}

extern "C" void kernel_launch(void* const* d_in, const int* in_sizes, int n_in,
                              void* d_out, int out_size){
  int iData, iEmbed, iW, iAtI, iAtJ, iAemI, iAemJ, iBias, iG1, iB1, iG2, iB2, iOW, iOB;
  if(n_in >= 15 && in_sizes[1] == 2048){
    iData=0; iEmbed=2; iW=3; iAtI=4; iAtJ=5; iAemI=6; iAemJ=7; iBias=8;
    iG1=9; iB1=10; iG2=11; iB2=12; iOW=13; iOB=14;
  } else {
    iData=0; iEmbed=1; iW=2; iAtI=3; iAtJ=4; iAemI=5; iAemJ=6; iBias=7;
    iG1=8; iB1=9; iG2=10; iB2=11; iOW=12; iOB=13;
  }
  const float* data  = (const float*)d_in[iData];
  const float* embed = (const float*)d_in[iEmbed];
  const float* W     = (const float*)d_in[iW];
  const float* atI   = (const float*)d_in[iAtI];
  const float* atJ   = (const float*)d_in[iAtJ];
  const float* aemI  = (const float*)d_in[iAemI];
  const float* aemJ  = (const float*)d_in[iAemJ];
  const float* bias  = (const float*)d_in[iBias];
  const float* g1    = (const float*)d_in[iG1];
  const float* b1    = (const float*)d_in[iB1];
  const float* g2    = (const float*)d_in[iG2];
  const float* b2    = (const float*)d_in[iB2];
  const float* outW  = (const float*)d_in[iOW];
  const float* outB  = (const float*)d_in[iOB];
  float* out = (float*)d_out;

  float *sc1, *sh1, *sc2, *sh2, *ps1, *pq1, *ps2, *pq2;
  cudaGetSymbolAddress((void**)&sc1, d_scale1);
  cudaGetSymbolAddress((void**)&sh1, d_shift1);
  cudaGetSymbolAddress((void**)&sc2, d_scale2);
  cudaGetSymbolAddress((void**)&sh2, d_shift2);
  cudaGetSymbolAddress((void**)&ps1, d_ps1);
  cudaGetSymbolAddress((void**)&pq1, d_pq1);
  cudaGetSymbolAddress((void**)&ps2, d_ps2);
  cudaGetSymbolAddress((void**)&pq2, d_pq2);

  cudaFuncSetAttribute(k_attn, cudaFuncAttributeMaxDynamicSharedMemorySize, ATTN_SMEM_BYTES);
  cudaFuncSetAttribute(k_gemm, cudaFuncAttributeMaxDynamicSharedMemorySize, GEMM_SMEM);

  k_embed<<<64, 256>>>(embed, aemI, aemJ);
  k_topk <<<64, 256>>>();
  k_gemm <<<BN/128, 256, GEMM_SMEM>>>(data, W, atI, atJ);
  k_attn <<<AGRID, 512, ATTN_SMEM_BYTES>>>(bias);
  k_red  <<<64, 256>>>(ps1, pq1, AGRID, g1, b1, sc1, sh1);
  k_h1   <<<H1_BLOCKS, 256>>>(embed);
  k_red  <<<64, 256>>>(ps2, pq2, H1_BLOCKS, g2, b2, sc2, sh2);
  k_out  <<<BN/16, 256>>>(embed, outW, outB, out);
}